// round 1
// baseline (speedup 1.0000x reference)
#include <cuda_runtime.h>
#include <math.h>

#define SEQ   2048
#define DM    2048
#define NH    32
#define NG    8
#define HD    64
#define BATCH 2
#define NTOK  (BATCH*SEQ)   // 4096
#define FTOT  3072          // 2048 q + 512 k + 512 v

// ---------------- scratch (static device globals; no allocation) ----------------
__device__ float g_P [(size_t)NTOK*FTOT];        // qkv projection output
__device__ float g_Q [(size_t)BATCH*NH*SEQ*HD];  // [b*NH+h][s][d], rope'd
__device__ float g_K [(size_t)BATCH*NG*SEQ*HD];  // [b*NG+g][s][d], rope'd
__device__ float g_V [(size_t)BATCH*NG*SEQ*HD];
__device__ float g_AO[(size_t)NTOK*DM];          // attention output, token-major
__device__ float g_cos[SEQ*32];
__device__ float g_sin[SEQ*32];

// ---------------- RoPE cos/sin table (fp64 angle for accuracy) ----------------
__global__ void rope_table_kernel() {
    int i = blockIdx.x*256 + threadIdx.x;
    if (i >= SEQ*32) return;
    int pos = i >> 5, j = i & 31;
    double theta = pow(10000.0, -(double)j / 32.0);
    double ang   = fmod((double)pos * theta, 6.283185307179586476925286766559);
    float c, s;
    sincosf((float)ang, &s, &c);
    g_cos[i] = c;
    g_sin[i] = s;
}

// ---------------- rope + scatter to attention layouts ----------------
__global__ void rope_scatter_kernel() {
    int idx = blockIdx.x*256 + threadIdx.x;
    if (idx >= NTOK*FTOT) return;
    int t = idx / FTOT;
    int f = idx - t*FTOT;
    int b = t >> 11;
    int s = t & (SEQ-1);
    float val = g_P[idx];
    int d = f & 63;
    if (f < 2560) {
        // q or k: rotate-half RoPE over head dim 64
        int j  = d & 31;
        float c  = g_cos[(s<<5) + j];
        float sn = g_sin[(s<<5) + j];
        float partner = g_P[idx + ((d & 32) ? -32 : 32)];
        float out = (d & 32) ? fmaf(partner, sn, val*c) : fmaf(-partner, sn, val*c);
        if (f < 2048) {
            int h = f >> 6;
            g_Q[(((size_t)(b*NH + h))*SEQ + s)*HD + d] = out;
        } else {
            int g = (f - 2048) >> 6;
            g_K[(((size_t)(b*NG + g))*SEQ + s)*HD + d] = out;
        }
    } else {
        int g = (f - 2560) >> 6;
        g_V[(((size_t)(b*NG + g))*SEQ + s)*HD + d] = val;
    }
}

// ---------------- fp32 SGEMM:  C[m, col_off+n] = sum_k A[m,k]*W[n,k] + bias[n] ----------------
// 128x128 block tile, BK=8, 8x8 per-thread, 256 threads.
__global__ __launch_bounds__(256, 2)
void sgemm_nt_kernel(const float* __restrict__ A, const float* __restrict__ W,
                     const float* __restrict__ bias, float* __restrict__ C,
                     int K, int ldc, int col_off)
{
    __shared__ float As[8][128];
    __shared__ float Bs[8][128];
    const int bm = blockIdx.y * 128;
    const int bn = blockIdx.x * 128;
    const int tid = threadIdx.x;
    const int tx = tid & 15, ty = tid >> 4;
    const int lr = tid >> 1;           // 0..127
    const int lk = (tid & 1) * 4;      // 0 or 4

    const float* Ap = A + (size_t)(bm + lr)*K + lk;
    const float* Wp = W + (size_t)(bn + lr)*K + lk;

    float acc[8][8];
#pragma unroll
    for (int i = 0; i < 8; i++)
#pragma unroll
        for (int j = 0; j < 8; j++) acc[i][j] = 0.f;

    for (int k0 = 0; k0 < K; k0 += 8) {
        float4 a = *(const float4*)(Ap + k0);
        float4 w = *(const float4*)(Wp + k0);
        __syncthreads();
        As[lk+0][lr] = a.x; As[lk+1][lr] = a.y; As[lk+2][lr] = a.z; As[lk+3][lr] = a.w;
        Bs[lk+0][lr] = w.x; Bs[lk+1][lr] = w.y; Bs[lk+2][lr] = w.z; Bs[lk+3][lr] = w.w;
        __syncthreads();
#pragma unroll
        for (int kk = 0; kk < 8; kk++) {
            float ra[8], rb[8];
            *(float4*)&ra[0] = *(const float4*)&As[kk][ty*8];
            *(float4*)&ra[4] = *(const float4*)&As[kk][ty*8 + 4];
            *(float4*)&rb[0] = *(const float4*)&Bs[kk][tx*8];
            *(float4*)&rb[4] = *(const float4*)&Bs[kk][tx*8 + 4];
#pragma unroll
            for (int i = 0; i < 8; i++)
#pragma unroll
                for (int j = 0; j < 8; j++)
                    acc[i][j] = fmaf(ra[i], rb[j], acc[i][j]);
        }
    }

#pragma unroll
    for (int i = 0; i < 8; i++) {
        int row = bm + ty*8 + i;
        float* cp = C + (size_t)row*ldc + col_off + bn + tx*8;
#pragma unroll
        for (int j = 0; j < 8; j += 4) {
            float4 o;
            o.x = acc[i][j+0] + bias[bn + tx*8 + j + 0];
            o.y = acc[i][j+1] + bias[bn + tx*8 + j + 1];
            o.z = acc[i][j+2] + bias[bn + tx*8 + j + 2];
            o.w = acc[i][j+3] + bias[bn + tx*8 + j + 3];
            *(float4*)(cp + j) = o;
        }
    }
}

// ---------------- flash-style causal GQA attention ----------------
// block = 256 threads (16x16), BQ=64 query rows, key tiles of 64.
// grid: (SEQ/64 = 32, BATCH*NH = 64)
__global__ __launch_bounds__(256, 1)
void attn_kernel()
{
    __shared__ float Qst[64][64];   // Q transposed: [d][q]
    __shared__ float KPs[64][64];   // K transposed [d][k]; reused as P [q][k]
    __shared__ float Vs [64][64];   // [k][d]

    const int qt = blockIdx.x;          // query tile
    const int bh = blockIdx.y;          // b*NH + h
    const int b  = bh >> 5;
    const int h  = bh & 31;
    const int g  = h >> 2;              // kv group (HPG=4)

    const float* Qp = g_Q + (((size_t)bh)*SEQ + qt*64) * HD;
    const float* Kp = g_K + ((size_t)(b*NG + g))*SEQ*HD;
    const float* Vp = g_V + ((size_t)(b*NG + g))*SEQ*HD;

    const int tid = threadIdx.x;
    const int tx = tid & 15, ty = tid >> 4;

    // load Q tile transposed
    for (int i = tid; i < 1024; i += 256) {
        int q = i >> 4, d4 = (i & 15) * 4;
        float4 v = *(const float4*)(Qp + q*64 + d4);
        Qst[d4+0][q] = v.x; Qst[d4+1][q] = v.y; Qst[d4+2][q] = v.z; Qst[d4+3][q] = v.w;
    }

    float acc[4][4];
    float m[4], l[4];
#pragma unroll
    for (int i = 0; i < 4; i++) {
        m[i] = -1e30f; l[i] = 0.f;
#pragma unroll
        for (int j = 0; j < 4; j++) acc[i][j] = 0.f;
    }

    const float scale = 0.125f;  // 1/sqrt(64)

    for (int kt = 0; kt <= qt; kt++) {
        __syncthreads();
        // load K (transposed) and V tiles
        for (int i = tid; i < 1024; i += 256) {
            int r = i >> 4, d4 = (i & 15) * 4;
            float4 kv = *(const float4*)(Kp + (size_t)(kt*64 + r)*64 + d4);
            KPs[d4+0][r] = kv.x; KPs[d4+1][r] = kv.y; KPs[d4+2][r] = kv.z; KPs[d4+3][r] = kv.w;
            float4 vv = *(const float4*)(Vp + (size_t)(kt*64 + r)*64 + d4);
            *(float4*)&Vs[r][d4] = vv;
        }
        __syncthreads();

        // scores: s[i][j] = q(ty*4+i) . k(tx*4+j)
        float s[4][4];
#pragma unroll
        for (int i = 0; i < 4; i++)
#pragma unroll
            for (int j = 0; j < 4; j++) s[i][j] = 0.f;
        for (int dd = 0; dd < 64; dd++) {
            float4 qv = *(const float4*)&Qst[dd][ty*4];
            float4 kv = *(const float4*)&KPs[dd][tx*4];
            float qa[4] = {qv.x, qv.y, qv.z, qv.w};
            float ka[4] = {kv.x, kv.y, kv.z, kv.w};
#pragma unroll
            for (int i = 0; i < 4; i++)
#pragma unroll
                for (int j = 0; j < 4; j++)
                    s[i][j] = fmaf(qa[i], ka[j], s[i][j]);
        }

        // scale + causal mask (only needed on diagonal tile)
        if (kt == qt) {
#pragma unroll
            for (int i = 0; i < 4; i++)
#pragma unroll
                for (int j = 0; j < 4; j++)
                    s[i][j] = (tx*4 + j <= ty*4 + i) ? s[i][j]*scale : -1e30f;
        } else {
#pragma unroll
            for (int i = 0; i < 4; i++)
#pragma unroll
                for (int j = 0; j < 4; j++) s[i][j] *= scale;
        }

        // online softmax per q row; row spread across 16 tx lanes (lane bits 0-3)
        float fsc[4];
#pragma unroll
        for (int i = 0; i < 4; i++) {
            float rm = fmaxf(fmaxf(s[i][0], s[i][1]), fmaxf(s[i][2], s[i][3]));
#pragma unroll
            for (int o = 8; o; o >>= 1) rm = fmaxf(rm, __shfl_xor_sync(0xffffffffu, rm, o));
            float mn = fmaxf(m[i], rm);
            fsc[i] = expf(m[i] - mn);
            float rs = 0.f;
#pragma unroll
            for (int j = 0; j < 4; j++) { s[i][j] = expf(s[i][j] - mn); rs += s[i][j]; }
#pragma unroll
            for (int o = 8; o; o >>= 1) rs += __shfl_xor_sync(0xffffffffu, rs, o);
            l[i] = l[i]*fsc[i] + rs;
            m[i] = mn;
#pragma unroll
            for (int j = 0; j < 4; j++) acc[i][j] *= fsc[i];
        }

        __syncthreads();   // all QK reads of KPs done
        // write P into KPs as [q][k]
#pragma unroll
        for (int i = 0; i < 4; i++)
            *(float4*)&KPs[ty*4 + i][tx*4] = make_float4(s[i][0], s[i][1], s[i][2], s[i][3]);
        __syncthreads();

        // acc[i][j] += sum_k P[q][k] * V[k][d]
        for (int k = 0; k < 64; k++) {
            float4 vv = *(const float4*)&Vs[k][tx*4];
            float va[4] = {vv.x, vv.y, vv.z, vv.w};
            float p0 = KPs[ty*4+0][k];
            float p1 = KPs[ty*4+1][k];
            float p2 = KPs[ty*4+2][k];
            float p3 = KPs[ty*4+3][k];
#pragma unroll
            for (int j = 0; j < 4; j++) {
                acc[0][j] = fmaf(p0, va[j], acc[0][j]);
                acc[1][j] = fmaf(p1, va[j], acc[1][j]);
                acc[2][j] = fmaf(p2, va[j], acc[2][j]);
                acc[3][j] = fmaf(p3, va[j], acc[3][j]);
            }
        }
    }

    // epilogue: normalize and write to g_AO[token][h*64 + d]
#pragma unroll
    for (int i = 0; i < 4; i++) {
        float inv = 1.f / l[i];
        int t = b*SEQ + qt*64 + ty*4 + i;
        float4 o = make_float4(acc[i][0]*inv, acc[i][1]*inv, acc[i][2]*inv, acc[i][3]*inv);
        *(float4*)&g_AO[(size_t)t*DM + h*64 + tx*4] = o;
    }
}

// ---------------- launch ----------------
extern "C" void kernel_launch(void* const* d_in, const int* in_sizes, int n_in,
                              void* d_out, int out_size)
{
    const float* x  = (const float*)d_in[0];
    const float* Wq = (const float*)d_in[1];
    const float* bq = (const float*)d_in[2];
    const float* Wk = (const float*)d_in[3];
    const float* bk = (const float*)d_in[4];
    const float* Wv = (const float*)d_in[5];
    const float* bv = (const float*)d_in[6];
    const float* Wo = (const float*)d_in[7];
    const float* bo = (const float*)d_in[8];
    float* out = (float*)d_out;

    float *pP = nullptr, *pAO = nullptr;
    cudaGetSymbolAddress((void**)&pP,  g_P);
    cudaGetSymbolAddress((void**)&pAO, g_AO);

    // QKV projections into g_P (cols: q[0:2048), k[2048:2560), v[2560:3072))
    sgemm_nt_kernel<<<dim3(DM/128,  NTOK/128), 256>>>(x, Wq, bq, pP, DM, FTOT, 0);
    sgemm_nt_kernel<<<dim3(512/128, NTOK/128), 256>>>(x, Wk, bk, pP, DM, FTOT, 2048);
    sgemm_nt_kernel<<<dim3(512/128, NTOK/128), 256>>>(x, Wv, bv, pP, DM, FTOT, 2560);

    rope_table_kernel<<<(SEQ*32 + 255)/256, 256>>>();
    rope_scatter_kernel<<<(NTOK*FTOT)/256, 256>>>();

    attn_kernel<<<dim3(SEQ/64, BATCH*NH), 256>>>();

    // output projection
    sgemm_nt_kernel<<<dim3(DM/128, NTOK/128), 256>>>(pAO, Wo, bo, out, DM, DM, 0);
}

// round 3
// speedup vs baseline: 1.6300x; 1.6300x over previous
#include <cuda_runtime.h>
#include <cuda_bf16.h>
#include <math.h>
#include <stdint.h>

#define SEQ   2048
#define DM    2048
#define NH    32
#define NG    8
#define HD    64
#define BATCH 2
#define NTOK  (BATCH*SEQ)   // 4096
#define FTOT  3072          // 2048 q + 512 k + 512 v
#define KP    (3*DM)        // 6144: split-precision concatenated K

// ---------------- scratch (static device globals; no allocation) ----------------
__device__ float g_P [(size_t)NTOK*FTOT];
__device__ float g_Q [(size_t)BATCH*NH*SEQ*HD];
__device__ float g_K [(size_t)BATCH*NG*SEQ*HD];
__device__ float g_V [(size_t)BATCH*NG*SEQ*HD];
__device__ float g_AO[(size_t)NTOK*DM];
__device__ float g_cos[SEQ*32];
__device__ float g_sin[SEQ*32];

// split-precision bf16 operands: act = [hi, lo, hi]; W = [hi, hi, lo]
__device__ __nv_bfloat16 g_xs [(size_t)NTOK*KP];
__device__ __nv_bfloat16 g_Wqs[(size_t)DM  *KP];
__device__ __nv_bfloat16 g_Wks[(size_t)512 *KP];
__device__ __nv_bfloat16 g_Wvs[(size_t)512 *KP];
__device__ __nv_bfloat16 g_Wos[(size_t)DM  *KP];
__device__ __nv_bfloat16 g_AOs[(size_t)NTOK*KP];

// ===================== helpers =====================
__device__ __forceinline__ uint32_t smem_u32(const void* p) {
    uint32_t a;
    asm("{ .reg .u64 t; cvta.to.shared.u64 t, %1; cvt.u32.u64 %0, t; }" : "=r"(a) : "l"(p));
    return a;
}
__device__ __forceinline__ void cp_async16(uint32_t dst, const void* src) {
    asm volatile("cp.async.cg.shared.global [%0], [%1], 16;" :: "r"(dst), "l"(src) : "memory");
}
#define CP_COMMIT() asm volatile("cp.async.commit_group;" ::: "memory")
#define CP_WAIT(n)  asm volatile("cp.async.wait_group %0;" :: "n"(n) : "memory")

__device__ __forceinline__ void ldsm4(uint32_t* r, uint32_t addr) {
    asm volatile("ldmatrix.sync.aligned.m8n8.x4.shared.b16 {%0,%1,%2,%3}, [%4];"
                 : "=r"(r[0]), "=r"(r[1]), "=r"(r[2]), "=r"(r[3]) : "r"(addr));
}
__device__ __forceinline__ void mma16816(float* d, const uint32_t* a, const uint32_t* b) {
    asm volatile("mma.sync.aligned.m16n8k16.row.col.f32.bf16.bf16.f32 "
                 "{%0,%1,%2,%3}, {%4,%5,%6,%7}, {%8,%9}, {%0,%1,%2,%3};"
                 : "+f"(d[0]), "+f"(d[1]), "+f"(d[2]), "+f"(d[3])
                 : "r"(a[0]), "r"(a[1]), "r"(a[2]), "r"(a[3]), "r"(b[0]), "r"(b[1]));
}

// smem tile: 128 rows x 32 bf16 (64B/row), swizzle: chunk' = chunk ^ ((row>>1)&3)
__device__ __forceinline__ uint32_t swz32(int row, int chunk) {
    return (uint32_t)(row*64 + ((chunk ^ ((row >> 1) & 3)) * 16));
}

// ===================== split-precision conversion =====================
__global__ void split_kernel(const float* __restrict__ src, __nv_bfloat16* __restrict__ dst,
                             int n, int isW)
{
    int idx = blockIdx.x*256 + threadIdx.x;
    if (idx >= n) return;
    int r = idx >> 11;
    int c = idx & 2047;
    float v = src[idx];
    __nv_bfloat16 hi = __float2bfloat16(v);
    __nv_bfloat16 lo = __float2bfloat16(v - __bfloat162float(hi));
    size_t base = (size_t)r * KP;
    if (isW) {
        dst[base + c] = hi; dst[base + DM + c] = hi; dst[base + 2*DM + c] = lo;
    } else {
        dst[base + c] = hi; dst[base + DM + c] = lo; dst[base + 2*DM + c] = hi;
    }
}

// ===================== HMMA bf16 GEMM: C[m, col_off+n] = A @ B^T + bias =====================
// A: [M, Kp] bf16 K-major; B: [N, Kp] bf16 K-major. Block tile 128x128x32, 8 warps (2x4).
__global__ __launch_bounds__(256, 2)
void gemm_mma_kernel(const __nv_bfloat16* __restrict__ A, const __nv_bfloat16* __restrict__ B,
                     const float* __restrict__ bias, float* __restrict__ C,
                     int Kp, int ldc, int col_off)
{
    __shared__ __nv_bfloat16 As[2][128*32];
    __shared__ __nv_bfloat16 Bs[2][128*32];

    const int tid  = threadIdx.x;
    const int lane = tid & 31;
    const int wid  = tid >> 5;
    const int wm   = wid >> 2;      // 0..1
    const int wn   = wid & 3;       // 0..3
    const int bm   = blockIdx.y * 128;
    const int bn   = blockIdx.x * 128;

    const uint32_t asb[2] = { smem_u32(As[0]), smem_u32(As[1]) };
    const uint32_t bsb[2] = { smem_u32(Bs[0]), smem_u32(Bs[1]) };

    // loader: 128 rows x 4 chunks(16B) per matrix = 512 cp.async; 256 thr -> 2 each
    const int lrow = tid >> 2;        // 0..63
    const int lc   = tid & 3;         // chunk

    float acc[4][4][4];
#pragma unroll
    for (int i = 0; i < 4; i++)
#pragma unroll
        for (int j = 0; j < 4; j++)
#pragma unroll
            for (int e = 0; e < 4; e++) acc[i][j][e] = 0.f;

    const int nk = Kp / 32;

    // prefetch tile 0
    {
        const __nv_bfloat16* Ap = A + (size_t)bm*Kp;
        const __nv_bfloat16* Bp = B + (size_t)bn*Kp;
#pragma unroll
        for (int h = 0; h < 2; h++) {
            int row = lrow + h*64;
            cp_async16(asb[0] + swz32(row, lc), Ap + (size_t)row*Kp + lc*8);
            cp_async16(bsb[0] + swz32(row, lc), Bp + (size_t)row*Kp + lc*8);
        }
        CP_COMMIT();
    }

    for (int t = 0; t < nk; t++) {
        const int st = t & 1;
        if (t + 1 < nk) {
            const __nv_bfloat16* Ap = A + (size_t)bm*Kp + (t+1)*32;
            const __nv_bfloat16* Bp = B + (size_t)bn*Kp + (t+1)*32;
#pragma unroll
            for (int h = 0; h < 2; h++) {
                int row = lrow + h*64;
                cp_async16(asb[st^1] + swz32(row, lc), Ap + (size_t)row*Kp + lc*8);
                cp_async16(bsb[st^1] + swz32(row, lc), Bp + (size_t)row*Kp + lc*8);
            }
            CP_COMMIT();
            CP_WAIT(1);
        } else {
            CP_WAIT(0);
        }
        __syncthreads();

#pragma unroll
        for (int ks = 0; ks < 2; ks++) {
            uint32_t afr[4][4];
#pragma unroll
            for (int mf = 0; mf < 4; mf++) {
                int row = wm*64 + mf*16 + (lane & 15);
                int ch  = ks*2 + (lane >> 4);
                ldsm4(afr[mf], asb[st] + swz32(row, ch));
            }
            uint32_t bfr[2][4];
#pragma unroll
            for (int nb = 0; nb < 2; nb++) {
                int row = wn*32 + nb*16 + ((lane >> 4) << 3) + (lane & 7);
                int ch  = ks*2 + ((lane >> 3) & 1);
                ldsm4(bfr[nb], bsb[st] + swz32(row, ch));
            }
#pragma unroll
            for (int mf = 0; mf < 4; mf++) {
#pragma unroll
                for (int nb = 0; nb < 2; nb++) {
                    mma16816(acc[mf][2*nb+0], afr[mf], &bfr[nb][0]);
                    mma16816(acc[mf][2*nb+1], afr[mf], &bfr[nb][2]);
                }
            }
        }
        __syncthreads();
    }

    // epilogue
#pragma unroll
    for (int mf = 0; mf < 4; mf++) {
        int m0 = bm + wm*64 + mf*16 + (lane >> 2);
#pragma unroll
        for (int nf = 0; nf < 4; nf++) {
            int nl = bn + wn*32 + nf*8 + 2*(lane & 3);
            float b0 = bias[nl], b1 = bias[nl+1];
            float2 v0 = make_float2(acc[mf][nf][0] + b0, acc[mf][nf][1] + b1);
            float2 v1 = make_float2(acc[mf][nf][2] + b0, acc[mf][nf][3] + b1);
            *(float2*)(C + (size_t)m0*ldc + col_off + nl)       = v0;
            *(float2*)(C + (size_t)(m0+8)*ldc + col_off + nl)   = v1;
        }
    }
}

// ===================== RoPE table (fp64 angle) =====================
__global__ void rope_table_kernel() {
    int i = blockIdx.x*256 + threadIdx.x;
    if (i >= SEQ*32) return;
    int pos = i >> 5, j = i & 31;
    double theta = pow(10000.0, -(double)j / 32.0);
    double ang   = fmod((double)pos * theta, 6.283185307179586476925286766559);
    float c, s;
    sincosf((float)ang, &s, &c);
    g_cos[i] = c;
    g_sin[i] = s;
}

// ===================== rope + scatter =====================
__global__ void rope_scatter_kernel() {
    int idx = blockIdx.x*256 + threadIdx.x;
    if (idx >= NTOK*FTOT) return;
    int t = idx / FTOT;
    int f = idx - t*FTOT;
    int b = t >> 11;
    int s = t & (SEQ-1);
    float val = g_P[idx];
    int d = f & 63;
    if (f < 2560) {
        int j  = d & 31;
        float c  = g_cos[(s<<5) + j];
        float sn = g_sin[(s<<5) + j];
        float partner = g_P[idx + ((d & 32) ? -32 : 32)];
        float out = (d & 32) ? fmaf(partner, sn, val*c) : fmaf(-partner, sn, val*c);
        if (f < 2048) {
            int h = f >> 6;
            g_Q[(((size_t)(b*NH + h))*SEQ + s)*HD + d] = out;
        } else {
            int g = (f - 2048) >> 6;
            g_K[(((size_t)(b*NG + g))*SEQ + s)*HD + d] = out;
        }
    } else {
        int g = (f - 2560) >> 6;
        g_V[(((size_t)(b*NG + g))*SEQ + s)*HD + d] = val;
    }
}

// ===================== flash-style causal GQA attention (fp32) =====================
__global__ __launch_bounds__(256, 1)
void attn_kernel()
{
    __shared__ float Qst[64][64];
    __shared__ float KPs[64][64];
    __shared__ float Vs [64][64];

    const int qt = blockIdx.x;
    const int bh = blockIdx.y;
    const int b  = bh >> 5;
    const int h  = bh & 31;
    const int g  = h >> 2;

    const float* Qp = g_Q + (((size_t)bh)*SEQ + qt*64) * HD;
    const float* Kp = g_K + ((size_t)(b*NG + g))*SEQ*HD;
    const float* Vp = g_V + ((size_t)(b*NG + g))*SEQ*HD;

    const int tid = threadIdx.x;
    const int tx = tid & 15, ty = tid >> 4;

    for (int i = tid; i < 1024; i += 256) {
        int q = i >> 4, d4 = (i & 15) * 4;
        float4 v = *(const float4*)(Qp + q*64 + d4);
        Qst[d4+0][q] = v.x; Qst[d4+1][q] = v.y; Qst[d4+2][q] = v.z; Qst[d4+3][q] = v.w;
    }

    float acc[4][4];
    float m[4], l[4];
#pragma unroll
    for (int i = 0; i < 4; i++) {
        m[i] = -1e30f; l[i] = 0.f;
#pragma unroll
        for (int j = 0; j < 4; j++) acc[i][j] = 0.f;
    }

    const float scale = 0.125f;

    for (int kt = 0; kt <= qt; kt++) {
        __syncthreads();
        for (int i = tid; i < 1024; i += 256) {
            int r = i >> 4, d4 = (i & 15) * 4;
            float4 kv = *(const float4*)(Kp + (size_t)(kt*64 + r)*64 + d4);
            KPs[d4+0][r] = kv.x; KPs[d4+1][r] = kv.y; KPs[d4+2][r] = kv.z; KPs[d4+3][r] = kv.w;
            float4 vv = *(const float4*)(Vp + (size_t)(kt*64 + r)*64 + d4);
            *(float4*)&Vs[r][d4] = vv;
        }
        __syncthreads();

        float s[4][4];
#pragma unroll
        for (int i = 0; i < 4; i++)
#pragma unroll
            for (int j = 0; j < 4; j++) s[i][j] = 0.f;
        for (int dd = 0; dd < 64; dd++) {
            float4 qv = *(const float4*)&Qst[dd][ty*4];
            float4 kv = *(const float4*)&KPs[dd][tx*4];
            float qa[4] = {qv.x, qv.y, qv.z, qv.w};
            float ka[4] = {kv.x, kv.y, kv.z, kv.w};
#pragma unroll
            for (int i = 0; i < 4; i++)
#pragma unroll
                for (int j = 0; j < 4; j++)
                    s[i][j] = fmaf(qa[i], ka[j], s[i][j]);
        }

        if (kt == qt) {
#pragma unroll
            for (int i = 0; i < 4; i++)
#pragma unroll
                for (int j = 0; j < 4; j++)
                    s[i][j] = (tx*4 + j <= ty*4 + i) ? s[i][j]*scale : -1e30f;
        } else {
#pragma unroll
            for (int i = 0; i < 4; i++)
#pragma unroll
                for (int j = 0; j < 4; j++) s[i][j] *= scale;
        }

        float fsc[4];
#pragma unroll
        for (int i = 0; i < 4; i++) {
            float rm = fmaxf(fmaxf(s[i][0], s[i][1]), fmaxf(s[i][2], s[i][3]));
#pragma unroll
            for (int o = 8; o; o >>= 1) rm = fmaxf(rm, __shfl_xor_sync(0xffffffffu, rm, o));
            float mn = fmaxf(m[i], rm);
            fsc[i] = expf(m[i] - mn);
            float rs = 0.f;
#pragma unroll
            for (int j = 0; j < 4; j++) { s[i][j] = expf(s[i][j] - mn); rs += s[i][j]; }
#pragma unroll
            for (int o = 8; o; o >>= 1) rs += __shfl_xor_sync(0xffffffffu, rs, o);
            l[i] = l[i]*fsc[i] + rs;
            m[i] = mn;
#pragma unroll
            for (int j = 0; j < 4; j++) acc[i][j] *= fsc[i];
        }

        __syncthreads();
#pragma unroll
        for (int i = 0; i < 4; i++)
            *(float4*)&KPs[ty*4 + i][tx*4] = make_float4(s[i][0], s[i][1], s[i][2], s[i][3]);
        __syncthreads();

        for (int k = 0; k < 64; k++) {
            float4 vv = *(const float4*)&Vs[k][tx*4];
            float va[4] = {vv.x, vv.y, vv.z, vv.w};
            float p0 = KPs[ty*4+0][k];
            float p1 = KPs[ty*4+1][k];
            float p2 = KPs[ty*4+2][k];
            float p3 = KPs[ty*4+3][k];
#pragma unroll
            for (int j = 0; j < 4; j++) {
                acc[0][j] = fmaf(p0, va[j], acc[0][j]);
                acc[1][j] = fmaf(p1, va[j], acc[1][j]);
                acc[2][j] = fmaf(p2, va[j], acc[2][j]);
                acc[3][j] = fmaf(p3, va[j], acc[3][j]);
            }
        }
    }

#pragma unroll
    for (int i = 0; i < 4; i++) {
        float inv = 1.f / l[i];
        int t = b*SEQ + qt*64 + ty*4 + i;
        float4 o = make_float4(acc[i][0]*inv, acc[i][1]*inv, acc[i][2]*inv, acc[i][3]*inv);
        *(float4*)&g_AO[(size_t)t*DM + h*64 + tx*4] = o;
    }
}

// ===================== launch =====================
extern "C" void kernel_launch(void* const* d_in, const int* in_sizes, int n_in,
                              void* d_out, int out_size)
{
    const float* x  = (const float*)d_in[0];
    const float* Wq = (const float*)d_in[1];
    const float* bq = (const float*)d_in[2];
    const float* Wk = (const float*)d_in[3];
    const float* bk = (const float*)d_in[4];
    const float* Wv = (const float*)d_in[5];
    const float* bv = (const float*)d_in[6];
    const float* Wo = (const float*)d_in[7];
    const float* bo = (const float*)d_in[8];
    float* out = (float*)d_out;

    float *pP = nullptr, *pAO = nullptr;
    __nv_bfloat16 *pxs, *pWqs, *pWks, *pWvs, *pWos, *pAOs;
    cudaGetSymbolAddress((void**)&pP,   g_P);
    cudaGetSymbolAddress((void**)&pAO,  g_AO);
    cudaGetSymbolAddress((void**)&pxs,  g_xs);
    cudaGetSymbolAddress((void**)&pWqs, g_Wqs);
    cudaGetSymbolAddress((void**)&pWks, g_Wks);
    cudaGetSymbolAddress((void**)&pWvs, g_Wvs);
    cudaGetSymbolAddress((void**)&pWos, g_Wos);
    cudaGetSymbolAddress((void**)&pAOs, g_AOs);

    // split-precision conversion
    split_kernel<<<(NTOK*DM)/256, 256>>>(x,  pxs,  NTOK*DM, 0);
    split_kernel<<<(DM*DM)/256,   256>>>(Wq, pWqs, DM*DM,   1);
    split_kernel<<<(512*DM)/256,  256>>>(Wk, pWks, 512*DM,  1);
    split_kernel<<<(512*DM)/256,  256>>>(Wv, pWvs, 512*DM,  1);
    split_kernel<<<(DM*DM)/256,   256>>>(Wo, pWos, DM*DM,   1);

    // QKV projections (cols: q[0:2048), k[2048:2560), v[2560:3072))
    gemm_mma_kernel<<<dim3(DM/128,  NTOK/128), 256>>>(pxs, pWqs, bq, pP, KP, FTOT, 0);
    gemm_mma_kernel<<<dim3(512/128, NTOK/128), 256>>>(pxs, pWks, bk, pP, KP, FTOT, 2048);
    gemm_mma_kernel<<<dim3(512/128, NTOK/128), 256>>>(pxs, pWvs, bv, pP, KP, FTOT, 2560);

    rope_table_kernel<<<(SEQ*32 + 255)/256, 256>>>();
    rope_scatter_kernel<<<(NTOK*FTOT)/256, 256>>>();

    attn_kernel<<<dim3(SEQ/64, BATCH*NH), 256>>>();

    // output projection
    split_kernel<<<(NTOK*DM)/256, 256>>>(pAO, pAOs, NTOK*DM, 0);
    gemm_mma_kernel<<<dim3(DM/128, NTOK/128), 256>>>(pAOs, pWos, bo, out, KP, DM, 0);
}

// round 9
// speedup vs baseline: 3.2985x; 2.0237x over previous
#include <cuda_runtime.h>
#include <cuda_bf16.h>
#include <cuda_fp16.h>
#include <math.h>
#include <stdint.h>

#define SEQ   2048
#define DM    2048
#define NH    32
#define NG    8
#define HD    64
#define BATCH 2
#define NTOK  (BATCH*SEQ)   // 4096
#define FTOT  3072          // 2048 q + 512 k + 512 v
#define KP    (3*DM)        // 6144: split-precision concatenated K

// fold softmax scale and log2(e) into Q (scores land in log2 domain)
#define QSC   (0.125f * 1.44269504088896340736f)

// ---------------- scratch (static device globals; no allocation) ----------------
__device__ float g_P [(size_t)NTOK*FTOT];
__device__ __half g_Qh[(size_t)BATCH*NH*SEQ*HD];
__device__ __half g_Kh[(size_t)BATCH*NG*SEQ*HD];
__device__ __half g_Vh[(size_t)BATCH*NG*SEQ*HD];
__device__ float g_AO[(size_t)NTOK*DM];
__device__ float g_cos[SEQ*32];
__device__ float g_sin[SEQ*32];

// split-precision bf16 operands: act = [hi, lo, hi]; W = [hi, hi, lo]
__device__ __nv_bfloat16 g_xs [(size_t)NTOK*KP];
__device__ __nv_bfloat16 g_Wqs[(size_t)DM  *KP];
__device__ __nv_bfloat16 g_Wks[(size_t)512 *KP];
__device__ __nv_bfloat16 g_Wvs[(size_t)512 *KP];
__device__ __nv_bfloat16 g_Wos[(size_t)DM  *KP];
__device__ __nv_bfloat16 g_AOs[(size_t)NTOK*KP];

// ===================== helpers =====================
__device__ __forceinline__ uint32_t smem_u32(const void* p) {
    uint32_t a;
    asm("{ .reg .u64 t; cvta.to.shared.u64 t, %1; cvt.u32.u64 %0, t; }" : "=r"(a) : "l"(p));
    return a;
}
__device__ __forceinline__ void cp_async16(uint32_t dst, const void* src) {
    asm volatile("cp.async.cg.shared.global [%0], [%1], 16;" :: "r"(dst), "l"(src) : "memory");
}
#define CP_COMMIT() asm volatile("cp.async.commit_group;" ::: "memory")
#define CP_WAIT(n)  asm volatile("cp.async.wait_group %0;" :: "n"(n) : "memory")

__device__ __forceinline__ void ldsm4(uint32_t* r, uint32_t addr) {
    asm volatile("ldmatrix.sync.aligned.m8n8.x4.shared.b16 {%0,%1,%2,%3}, [%4];"
                 : "=r"(r[0]), "=r"(r[1]), "=r"(r[2]), "=r"(r[3]) : "r"(addr));
}
__device__ __forceinline__ void ldsm4t(uint32_t* r, uint32_t addr) {
    asm volatile("ldmatrix.sync.aligned.m8n8.x4.trans.shared.b16 {%0,%1,%2,%3}, [%4];"
                 : "=r"(r[0]), "=r"(r[1]), "=r"(r[2]), "=r"(r[3]) : "r"(addr));
}
__device__ __forceinline__ void mma16816(float* d, const uint32_t* a, const uint32_t* b) {
    asm volatile("mma.sync.aligned.m16n8k16.row.col.f32.bf16.bf16.f32 "
                 "{%0,%1,%2,%3}, {%4,%5,%6,%7}, {%8,%9}, {%0,%1,%2,%3};"
                 : "+f"(d[0]), "+f"(d[1]), "+f"(d[2]), "+f"(d[3])
                 : "r"(a[0]), "r"(a[1]), "r"(a[2]), "r"(a[3]), "r"(b[0]), "r"(b[1]));
}
__device__ __forceinline__ void mma16816h(float* d, const uint32_t* a, const uint32_t* b) {
    asm volatile("mma.sync.aligned.m16n8k16.row.col.f32.f16.f16.f32 "
                 "{%0,%1,%2,%3}, {%4,%5,%6,%7}, {%8,%9}, {%0,%1,%2,%3};"
                 : "+f"(d[0]), "+f"(d[1]), "+f"(d[2]), "+f"(d[3])
                 : "r"(a[0]), "r"(a[1]), "r"(a[2]), "r"(a[3]), "r"(b[0]), "r"(b[1]));
}
// pack two fp32 -> fp16x2 in one u32
__device__ __forceinline__ uint32_t pack_f16x2(float lo, float hi) {
    uint32_t r;
    asm("cvt.rn.f16x2.f32 %0, %1, %2;" : "=r"(r) : "f"(hi), "f"(lo));
    return r;
}

// GEMM smem tile: rows x 32 bf16 (64B/row), swizzle: chunk' = chunk ^ ((row>>1)&3)
__device__ __forceinline__ uint32_t swz32(int row, int chunk) {
    return (uint32_t)(row*64 + ((chunk ^ ((row >> 1) & 3)) * 16));
}
// attention smem tile: rows of 64 halves (128B), SW128 swizzle: ch' = ch ^ (row&7)
__device__ __forceinline__ uint32_t hswz(int row, int ch) {
    return (uint32_t)(row*128 + ((ch ^ (row & 7)) * 16));
}

// ===================== split-precision conversion =====================
__global__ void split_kernel(const float* __restrict__ src, __nv_bfloat16* __restrict__ dst,
                             int n, int isW)
{
    int idx = blockIdx.x*256 + threadIdx.x;
    if (idx >= n) return;
    int r = idx >> 11;
    int c = idx & 2047;
    float v = src[idx];
    __nv_bfloat16 hi = __float2bfloat16(v);
    __nv_bfloat16 lo = __float2bfloat16(v - __bfloat162float(hi));
    size_t base = (size_t)r * KP;
    if (isW) {
        dst[base + c] = hi; dst[base + DM + c] = hi; dst[base + 2*DM + c] = lo;
    } else {
        dst[base + c] = hi; dst[base + DM + c] = lo; dst[base + 2*DM + c] = hi;
    }
}

// ===================== HMMA bf16 GEMM: C[m, col_off+n] = A @ B^T + bias =====================
__global__ __launch_bounds__(256, 2)
void gemm_mma_kernel(const __nv_bfloat16* __restrict__ A, const __nv_bfloat16* __restrict__ B,
                     const float* __restrict__ bias, float* __restrict__ C,
                     int Kp, int ldc, int col_off)
{
    __shared__ __nv_bfloat16 As[2][128*32];
    __shared__ __nv_bfloat16 Bs[2][128*32];

    const int tid  = threadIdx.x;
    const int lane = tid & 31;
    const int wid  = tid >> 5;
    const int wm   = wid >> 2;
    const int wn   = wid & 3;
    const int bm   = blockIdx.y * 128;
    const int bn   = blockIdx.x * 128;

    const uint32_t asb[2] = { smem_u32(As[0]), smem_u32(As[1]) };
    const uint32_t bsb[2] = { smem_u32(Bs[0]), smem_u32(Bs[1]) };

    const int lrow = tid >> 2;
    const int lc   = tid & 3;

    float acc[4][4][4];
#pragma unroll
    for (int i = 0; i < 4; i++)
#pragma unroll
        for (int j = 0; j < 4; j++)
#pragma unroll
            for (int e = 0; e < 4; e++) acc[i][j][e] = 0.f;

    const int nk = Kp / 32;

    {
        const __nv_bfloat16* Ap = A + (size_t)bm*Kp;
        const __nv_bfloat16* Bp = B + (size_t)bn*Kp;
#pragma unroll
        for (int h = 0; h < 2; h++) {
            int row = lrow + h*64;
            cp_async16(asb[0] + swz32(row, lc), Ap + (size_t)row*Kp + lc*8);
            cp_async16(bsb[0] + swz32(row, lc), Bp + (size_t)row*Kp + lc*8);
        }
        CP_COMMIT();
    }

    for (int t = 0; t < nk; t++) {
        const int st = t & 1;
        if (t + 1 < nk) {
            const __nv_bfloat16* Ap = A + (size_t)bm*Kp + (t+1)*32;
            const __nv_bfloat16* Bp = B + (size_t)bn*Kp + (t+1)*32;
#pragma unroll
            for (int h = 0; h < 2; h++) {
                int row = lrow + h*64;
                cp_async16(asb[st^1] + swz32(row, lc), Ap + (size_t)row*Kp + lc*8);
                cp_async16(bsb[st^1] + swz32(row, lc), Bp + (size_t)row*Kp + lc*8);
            }
            CP_COMMIT();
            CP_WAIT(1);
        } else {
            CP_WAIT(0);
        }
        __syncthreads();

#pragma unroll
        for (int ks = 0; ks < 2; ks++) {
            uint32_t afr[4][4];
#pragma unroll
            for (int mf = 0; mf < 4; mf++) {
                int row = wm*64 + mf*16 + (lane & 15);
                int ch  = ks*2 + (lane >> 4);
                ldsm4(afr[mf], asb[st] + swz32(row, ch));
            }
            uint32_t bfr[2][4];
#pragma unroll
            for (int nb = 0; nb < 2; nb++) {
                int row = wn*32 + nb*16 + ((lane >> 4) << 3) + (lane & 7);
                int ch  = ks*2 + ((lane >> 3) & 1);
                ldsm4(bfr[nb], bsb[st] + swz32(row, ch));
            }
#pragma unroll
            for (int mf = 0; mf < 4; mf++) {
#pragma unroll
                for (int nb = 0; nb < 2; nb++) {
                    mma16816(acc[mf][2*nb+0], afr[mf], &bfr[nb][0]);
                    mma16816(acc[mf][2*nb+1], afr[mf], &bfr[nb][2]);
                }
            }
        }
        __syncthreads();
    }

#pragma unroll
    for (int mf = 0; mf < 4; mf++) {
        int m0 = bm + wm*64 + mf*16 + (lane >> 2);
#pragma unroll
        for (int nf = 0; nf < 4; nf++) {
            int nl = bn + wn*32 + nf*8 + 2*(lane & 3);
            float b0 = bias[nl], b1 = bias[nl+1];
            float2 v0 = make_float2(acc[mf][nf][0] + b0, acc[mf][nf][1] + b1);
            float2 v1 = make_float2(acc[mf][nf][2] + b0, acc[mf][nf][3] + b1);
            *(float2*)(C + (size_t)m0*ldc + col_off + nl)       = v0;
            *(float2*)(C + (size_t)(m0+8)*ldc + col_off + nl)   = v1;
        }
    }
}

// ===================== RoPE table (fp64 angle) =====================
__global__ void rope_table_kernel() {
    int i = blockIdx.x*256 + threadIdx.x;
    if (i >= SEQ*32) return;
    int pos = i >> 5, j = i & 31;
    double theta = pow(10000.0, -(double)j / 32.0);
    double ang   = fmod((double)pos * theta, 6.283185307179586476925286766559);
    float c, s;
    sincosf((float)ang, &s, &c);
    g_cos[i] = c;
    g_sin[i] = s;
}

// ===================== rope + scatter to fp16 attention layouts =====================
__global__ void rope_scatter_kernel() {
    int idx = blockIdx.x*256 + threadIdx.x;
    if (idx >= NTOK*FTOT) return;
    int t = idx / FTOT;
    int f = idx - t*FTOT;
    int b = t >> 11;
    int s = t & (SEQ-1);
    float val = g_P[idx];
    int d = f & 63;
    if (f < 2560) {
        int j  = d & 31;
        float c  = g_cos[(s<<5) + j];
        float sn = g_sin[(s<<5) + j];
        float partner = g_P[idx + ((d & 32) ? -32 : 32)];
        float out = (d & 32) ? fmaf(partner, sn, val*c) : fmaf(-partner, sn, val*c);
        if (f < 2048) {
            int h = f >> 6;
            g_Qh[(((size_t)(b*NH + h))*SEQ + s)*HD + d] = __float2half_rn(out * QSC);
        } else {
            int g = (f - 2048) >> 6;
            g_Kh[(((size_t)(b*NG + g))*SEQ + s)*HD + d] = __float2half_rn(out);
        }
    } else {
        int g = (f - 2560) >> 6;
        g_Vh[(((size_t)(b*NG + g))*SEQ + s)*HD + d] = __float2half_rn(val);
    }
}

// ===================== fp16 HMMA flash attention =====================
// BQ=128 (8 warps x 16 rows), BK=64, double-buffered K/V.
// grid: (SEQ/128 = 16, BATCH*NH = 64)
__global__ __launch_bounds__(256)
void attn_mma_kernel()
{
    __shared__ __half Qs[128*64];
    __shared__ __half Ks[2][64*64];
    __shared__ __half Vs[2][64*64];

    const int tid = threadIdx.x, lane = tid & 31, wid = tid >> 5;
    const int qt = blockIdx.x, bh = blockIdx.y;
    const int b = bh >> 5, h = bh & 31, g = h >> 2;

    const __half* Qp = g_Qh + ((size_t)bh*SEQ + qt*128)*HD;
    const __half* Kp = g_Kh + ((size_t)(b*NG + g))*SEQ*HD;
    const __half* Vp = g_Vh + ((size_t)(b*NG + g))*SEQ*HD;

    const uint32_t qsb = smem_u32(Qs);
    const uint32_t ksb[2] = { smem_u32(Ks[0]), smem_u32(Ks[1]) };
    const uint32_t vsb[2] = { smem_u32(Vs[0]), smem_u32(Vs[1]) };

    // load Q (128 rows x 8 chunks) + prefetch K/V tile 0, one commit group
    {
        int r = tid >> 1, cb = (tid & 1) * 4;
#pragma unroll
        for (int c = 0; c < 4; c++)
            cp_async16(qsb + hswz(r, cb + c), Qp + r*64 + (cb + c)*8);
        int kr = tid >> 2, kc = (tid & 3) * 2;
#pragma unroll
        for (int c = 0; c < 2; c++) {
            cp_async16(ksb[0] + hswz(kr, kc + c), Kp + (size_t)kr*64 + (kc + c)*8);
            cp_async16(vsb[0] + hswz(kr, kc + c), Vp + (size_t)kr*64 + (kc + c)*8);
        }
        CP_COMMIT();
    }

    float o[8][4];
    float m[2] = {-1e30f, -1e30f}, l[2] = {0.f, 0.f};
#pragma unroll
    for (int f = 0; f < 8; f++)
#pragma unroll
        for (int e = 0; e < 4; e++) o[f][e] = 0.f;

    uint32_t qf[4][4];
    const int nkt = 2*qt + 2;

    for (int kt = 0; kt < nkt; kt++) {
        const int st = kt & 1;
        if (kt + 1 < nkt) {
            int kr = tid >> 2, kc = (tid & 3) * 2;
            const __half* Kn = Kp + (size_t)(kt + 1)*64*64;
            const __half* Vn = Vp + (size_t)(kt + 1)*64*64;
#pragma unroll
            for (int c = 0; c < 2; c++) {
                cp_async16(ksb[st^1] + hswz(kr, kc + c), Kn + (size_t)kr*64 + (kc + c)*8);
                cp_async16(vsb[st^1] + hswz(kr, kc + c), Vn + (size_t)kr*64 + (kc + c)*8);
            }
            CP_COMMIT();
            CP_WAIT(1);
        } else {
            CP_WAIT(0);
        }
        __syncthreads();

        if (kt == 0) {
#pragma unroll
            for (int kk = 0; kk < 4; kk++)
                ldsm4(qf[kk], qsb + hswz(wid*16 + (lane & 15), kk*2 + (lane >> 4)));
        }

        // S = Q K^T  (in log2 units; scale folded into Q)
        float s[8][4];
#pragma unroll
        for (int f = 0; f < 8; f++)
#pragma unroll
            for (int e = 0; e < 4; e++) s[f][e] = 0.f;

#pragma unroll
        for (int kk = 0; kk < 4; kk++) {
#pragma unroll
            for (int tb2 = 0; tb2 < 4; tb2++) {
                uint32_t kb[4];
                ldsm4(kb, ksb[st] + hswz((tb2*2 + ((lane >> 4) & 1))*8 + (lane & 7),
                                         kk*2 + ((lane >> 3) & 1)));
                mma16816h(s[tb2*2 + 0], qf[kk], &kb[0]);
                mma16816h(s[tb2*2 + 1], qf[kk], &kb[2]);
            }
        }

        // causal mask (only tiles that touch/cross the diagonal for this warp)
        if (kt*64 + 63 > qt*128 + wid*16) {
            int r0 = qt*128 + wid*16 + (lane >> 2);
#pragma unroll
            for (int f = 0; f < 8; f++) {
                int c0 = kt*64 + f*8 + (lane & 3)*2;
#pragma unroll
                for (int e = 0; e < 4; e++) {
                    int row = r0 + ((e >> 1) << 3);
                    int col = c0 + (e & 1);
                    if (col > row) s[f][e] = -1e30f;
                }
            }
        }

        // online softmax (base 2)
        float fsc[2];
#pragma unroll
        for (int rh = 0; rh < 2; rh++) {
            float mx = m[rh];
#pragma unroll
            for (int f = 0; f < 8; f++)
                mx = fmaxf(mx, fmaxf(s[f][2*rh], s[f][2*rh + 1]));
            mx = fmaxf(mx, __shfl_xor_sync(0xffffffffu, mx, 1));
            mx = fmaxf(mx, __shfl_xor_sync(0xffffffffu, mx, 2));
            fsc[rh] = exp2f(m[rh] - mx);
            float rs = 0.f;
#pragma unroll
            for (int f = 0; f < 8; f++) {
                s[f][2*rh]     = exp2f(s[f][2*rh]     - mx);
                s[f][2*rh + 1] = exp2f(s[f][2*rh + 1] - mx);
                rs += s[f][2*rh] + s[f][2*rh + 1];
            }
            rs += __shfl_xor_sync(0xffffffffu, rs, 1);
            rs += __shfl_xor_sync(0xffffffffu, rs, 2);
            l[rh] = l[rh]*fsc[rh] + rs;
            m[rh] = mx;
        }
#pragma unroll
        for (int f = 0; f < 8; f++) {
            o[f][0] *= fsc[0]; o[f][1] *= fsc[0];
            o[f][2] *= fsc[1]; o[f][3] *= fsc[1];
        }

        // P -> fp16 A-frags
        uint32_t pa[4][4];
#pragma unroll
        for (int kk = 0; kk < 4; kk++) {
            pa[kk][0] = pack_f16x2(s[2*kk][0],   s[2*kk][1]);
            pa[kk][1] = pack_f16x2(s[2*kk][2],   s[2*kk][3]);
            pa[kk][2] = pack_f16x2(s[2*kk+1][0], s[2*kk+1][1]);
            pa[kk][3] = pack_f16x2(s[2*kk+1][2], s[2*kk+1][3]);
        }

        // O += P V
#pragma unroll
        for (int kk = 0; kk < 4; kk++) {
#pragma unroll
            for (int db2 = 0; db2 < 4; db2++) {
                uint32_t vb[4];
                ldsm4t(vb, vsb[st] + hswz(kk*16 + ((lane >> 3) & 1)*8 + (lane & 7),
                                          db2*2 + ((lane >> 4) & 1)));
                mma16816h(o[db2*2 + 0], pa[kk], &vb[0]);
                mma16816h(o[db2*2 + 1], pa[kk], &vb[2]);
            }
        }
        __syncthreads();
    }

    // epilogue
    float inv0 = 1.f / l[0], inv1 = 1.f / l[1];
    int r0 = qt*128 + wid*16 + (lane >> 2);
    int t0 = b*SEQ + r0;
#pragma unroll
    for (int f = 0; f < 8; f++) {
        int d = h*64 + f*8 + (lane & 3)*2;
        *(float2*)&g_AO[(size_t)t0*DM + d]     = make_float2(o[f][0]*inv0, o[f][1]*inv0);
        *(float2*)&g_AO[(size_t)(t0+8)*DM + d] = make_float2(o[f][2]*inv1, o[f][3]*inv1);
    }
}

// ===================== launch =====================
extern "C" void kernel_launch(void* const* d_in, const int* in_sizes, int n_in,
                              void* d_out, int out_size)
{
    const float* x  = (const float*)d_in[0];
    const float* Wq = (const float*)d_in[1];
    const float* bq = (const float*)d_in[2];
    const float* Wk = (const float*)d_in[3];
    const float* bk = (const float*)d_in[4];
    const float* Wv = (const float*)d_in[5];
    const float* bv = (const float*)d_in[6];
    const float* Wo = (const float*)d_in[7];
    const float* bo = (const float*)d_in[8];
    float* out = (float*)d_out;

    float *pP = nullptr, *pAO = nullptr;
    __nv_bfloat16 *pxs, *pWqs, *pWks, *pWvs, *pWos, *pAOs;
    cudaGetSymbolAddress((void**)&pP,   g_P);
    cudaGetSymbolAddress((void**)&pAO,  g_AO);
    cudaGetSymbolAddress((void**)&pxs,  g_xs);
    cudaGetSymbolAddress((void**)&pWqs, g_Wqs);
    cudaGetSymbolAddress((void**)&pWks, g_Wks);
    cudaGetSymbolAddress((void**)&pWvs, g_Wvs);
    cudaGetSymbolAddress((void**)&pWos, g_Wos);
    cudaGetSymbolAddress((void**)&pAOs, g_AOs);

    // split-precision conversion
    split_kernel<<<(NTOK*DM)/256, 256>>>(x,  pxs,  NTOK*DM, 0);
    split_kernel<<<(DM*DM)/256,   256>>>(Wq, pWqs, DM*DM,   1);
    split_kernel<<<(512*DM)/256,  256>>>(Wk, pWks, 512*DM,  1);
    split_kernel<<<(512*DM)/256,  256>>>(Wv, pWvs, 512*DM,  1);
    split_kernel<<<(DM*DM)/256,   256>>>(Wo, pWos, DM*DM,   1);

    // QKV projections (cols: q[0:2048), k[2048:2560), v[2560:3072))
    gemm_mma_kernel<<<dim3(DM/128,  NTOK/128), 256>>>(pxs, pWqs, bq, pP, KP, FTOT, 0);
    gemm_mma_kernel<<<dim3(512/128, NTOK/128), 256>>>(pxs, pWks, bk, pP, KP, FTOT, 2048);
    gemm_mma_kernel<<<dim3(512/128, NTOK/128), 256>>>(pxs, pWvs, bv, pP, KP, FTOT, 2560);

    rope_table_kernel<<<(SEQ*32 + 255)/256, 256>>>();
    rope_scatter_kernel<<<(NTOK*FTOT)/256, 256>>>();

    attn_mma_kernel<<<dim3(SEQ/128, BATCH*NH), 256>>>();

    // output projection
    split_kernel<<<(NTOK*DM)/256, 256>>>(pAO, pAOs, NTOK*DM, 0);
    gemm_mma_kernel<<<dim3(DM/128, NTOK/128), 256>>>(pAOs, pWos, bo, out, KP, DM, 0);
}

// round 10
// speedup vs baseline: 7.0233x; 2.1292x over previous
#include <cuda_runtime.h>
#include <cuda_fp16.h>
#include <math.h>
#include <stdint.h>

#define SEQ   2048
#define DM    2048
#define NH    32
#define NG    8
#define HD    64
#define BATCH 2
#define NTOK  (BATCH*SEQ)   // 4096
#define FTOT  3072          // 2048 q + 512 k + 512 v

// fold softmax scale and log2(e) into Q (scores land in log2 domain)
#define QSC   (0.125f * 1.44269504088896340736f)

// ---------------- scratch (static device globals; no allocation) ----------------
__device__ float  g_P  [(size_t)NTOK*FTOT];        // qkv projection output (fp32)
__device__ __half g_Qh [(size_t)BATCH*NH*SEQ*HD];
__device__ __half g_Kh [(size_t)BATCH*NG*SEQ*HD];
__device__ __half g_Vh [(size_t)BATCH*NG*SEQ*HD];
__device__ __half g_AOh[(size_t)NTOK*DM];          // attention out (fp16, token-major)
__device__ float  g_cos[SEQ*32];
__device__ float  g_sin[SEQ*32];

// fp16 operands for GEMMs
__device__ __half g_xh [(size_t)NTOK*DM];
__device__ __half g_Wqh[(size_t)DM *DM];
__device__ __half g_Wkh[(size_t)512*DM];
__device__ __half g_Wvh[(size_t)512*DM];
__device__ __half g_Woh[(size_t)DM *DM];

// ===================== helpers =====================
__device__ __forceinline__ uint32_t smem_u32(const void* p) {
    uint32_t a;
    asm("{ .reg .u64 t; cvta.to.shared.u64 t, %1; cvt.u32.u64 %0, t; }" : "=r"(a) : "l"(p));
    return a;
}
__device__ __forceinline__ void cp_async16(uint32_t dst, const void* src) {
    asm volatile("cp.async.cg.shared.global [%0], [%1], 16;" :: "r"(dst), "l"(src) : "memory");
}
#define CP_COMMIT() asm volatile("cp.async.commit_group;" ::: "memory")
#define CP_WAIT(n)  asm volatile("cp.async.wait_group %0;" :: "n"(n) : "memory")

__device__ __forceinline__ void ldsm4(uint32_t* r, uint32_t addr) {
    asm volatile("ldmatrix.sync.aligned.m8n8.x4.shared.b16 {%0,%1,%2,%3}, [%4];"
                 : "=r"(r[0]), "=r"(r[1]), "=r"(r[2]), "=r"(r[3]) : "r"(addr));
}
__device__ __forceinline__ void ldsm4t(uint32_t* r, uint32_t addr) {
    asm volatile("ldmatrix.sync.aligned.m8n8.x4.trans.shared.b16 {%0,%1,%2,%3}, [%4];"
                 : "=r"(r[0]), "=r"(r[1]), "=r"(r[2]), "=r"(r[3]) : "r"(addr));
}
__device__ __forceinline__ void mma16816h(float* d, const uint32_t* a, const uint32_t* b) {
    asm volatile("mma.sync.aligned.m16n8k16.row.col.f32.f16.f16.f32 "
                 "{%0,%1,%2,%3}, {%4,%5,%6,%7}, {%8,%9}, {%0,%1,%2,%3};"
                 : "+f"(d[0]), "+f"(d[1]), "+f"(d[2]), "+f"(d[3])
                 : "r"(a[0]), "r"(a[1]), "r"(a[2]), "r"(a[3]), "r"(b[0]), "r"(b[1]));
}
// pack two fp32 -> fp16x2 in one u32 (lo goes to low half)
__device__ __forceinline__ uint32_t pack_f16x2(float lo, float hi) {
    uint32_t r;
    asm("cvt.rn.f16x2.f32 %0, %1, %2;" : "=r"(r) : "f"(hi), "f"(lo));
    return r;
}

// GEMM smem tile: rows x 32 halves (64B/row), swizzle: chunk' = chunk ^ ((row>>1)&3)
__device__ __forceinline__ uint32_t swz32(int row, int chunk) {
    return (uint32_t)(row*64 + ((chunk ^ ((row >> 1) & 3)) * 16));
}
// attention smem tile: rows of 64 halves (128B), SW128 swizzle: ch' = ch ^ (row&7)
__device__ __forceinline__ uint32_t hswz(int row, int ch) {
    return (uint32_t)(row*128 + ((ch ^ (row & 7)) * 16));
}

// ===================== fp32 -> fp16 conversion (pairwise) =====================
__global__ void tohalf_kernel(const float* __restrict__ src, uint32_t* __restrict__ dst, int npairs)
{
    int i = blockIdx.x*256 + threadIdx.x;
    if (i >= npairs) return;
    float2 v = ((const float2*)src)[i];
    dst[i] = pack_f16x2(v.x, v.y);
}

// ===================== HMMA fp16 GEMM: C[m, col_off+n] = A @ B^T + bias =====================
// A: [M, Kp] fp16 K-major; B: [N, Kp] fp16 K-major. Block tile 128x128x32, 8 warps (2x4).
__global__ __launch_bounds__(256, 2)
void gemm_mma_kernel(const __half* __restrict__ A, const __half* __restrict__ B,
                     const float* __restrict__ bias, float* __restrict__ C,
                     int Kp, int ldc, int col_off)
{
    __shared__ __half As[2][128*32];
    __shared__ __half Bs[2][128*32];

    const int tid  = threadIdx.x;
    const int lane = tid & 31;
    const int wid  = tid >> 5;
    const int wm   = wid >> 2;
    const int wn   = wid & 3;
    const int bm   = blockIdx.y * 128;
    const int bn   = blockIdx.x * 128;

    const uint32_t asb[2] = { smem_u32(As[0]), smem_u32(As[1]) };
    const uint32_t bsb[2] = { smem_u32(Bs[0]), smem_u32(Bs[1]) };

    const int lrow = tid >> 2;
    const int lc   = tid & 3;

    float acc[4][4][4];
#pragma unroll
    for (int i = 0; i < 4; i++)
#pragma unroll
        for (int j = 0; j < 4; j++)
#pragma unroll
            for (int e = 0; e < 4; e++) acc[i][j][e] = 0.f;

    const int nk = Kp / 32;

    {
        const __half* Ap = A + (size_t)bm*Kp;
        const __half* Bp = B + (size_t)bn*Kp;
#pragma unroll
        for (int h = 0; h < 2; h++) {
            int row = lrow + h*64;
            cp_async16(asb[0] + swz32(row, lc), Ap + (size_t)row*Kp + lc*8);
            cp_async16(bsb[0] + swz32(row, lc), Bp + (size_t)row*Kp + lc*8);
        }
        CP_COMMIT();
    }

    for (int t = 0; t < nk; t++) {
        const int st = t & 1;
        if (t + 1 < nk) {
            const __half* Ap = A + (size_t)bm*Kp + (t+1)*32;
            const __half* Bp = B + (size_t)bn*Kp + (t+1)*32;
#pragma unroll
            for (int h = 0; h < 2; h++) {
                int row = lrow + h*64;
                cp_async16(asb[st^1] + swz32(row, lc), Ap + (size_t)row*Kp + lc*8);
                cp_async16(bsb[st^1] + swz32(row, lc), Bp + (size_t)row*Kp + lc*8);
            }
            CP_COMMIT();
            CP_WAIT(1);
        } else {
            CP_WAIT(0);
        }
        __syncthreads();

#pragma unroll
        for (int ks = 0; ks < 2; ks++) {
            uint32_t afr[4][4];
#pragma unroll
            for (int mf = 0; mf < 4; mf++) {
                int row = wm*64 + mf*16 + (lane & 15);
                int ch  = ks*2 + (lane >> 4);
                ldsm4(afr[mf], asb[st] + swz32(row, ch));
            }
            uint32_t bfr[2][4];
#pragma unroll
            for (int nb = 0; nb < 2; nb++) {
                int row = wn*32 + nb*16 + ((lane >> 4) << 3) + (lane & 7);
                int ch  = ks*2 + ((lane >> 3) & 1);
                ldsm4(bfr[nb], bsb[st] + swz32(row, ch));
            }
#pragma unroll
            for (int mf = 0; mf < 4; mf++) {
#pragma unroll
                for (int nb = 0; nb < 2; nb++) {
                    mma16816h(acc[mf][2*nb+0], afr[mf], &bfr[nb][0]);
                    mma16816h(acc[mf][2*nb+1], afr[mf], &bfr[nb][2]);
                }
            }
        }
        __syncthreads();
    }

#pragma unroll
    for (int mf = 0; mf < 4; mf++) {
        int m0 = bm + wm*64 + mf*16 + (lane >> 2);
#pragma unroll
        for (int nf = 0; nf < 4; nf++) {
            int nl = bn + wn*32 + nf*8 + 2*(lane & 3);
            float b0 = bias[nl], b1 = bias[nl+1];
            float2 v0 = make_float2(acc[mf][nf][0] + b0, acc[mf][nf][1] + b1);
            float2 v1 = make_float2(acc[mf][nf][2] + b0, acc[mf][nf][3] + b1);
            *(float2*)(C + (size_t)m0*ldc + col_off + nl)       = v0;
            *(float2*)(C + (size_t)(m0+8)*ldc + col_off + nl)   = v1;
        }
    }
}

// ===================== RoPE table (fp64 angle) =====================
__global__ void rope_table_kernel() {
    int i = blockIdx.x*256 + threadIdx.x;
    if (i >= SEQ*32) return;
    int pos = i >> 5, j = i & 31;
    double theta = pow(10000.0, -(double)j / 32.0);
    double ang   = fmod((double)pos * theta, 6.283185307179586476925286766559);
    float c, s;
    sincosf((float)ang, &s, &c);
    g_cos[i] = c;
    g_sin[i] = s;
}

// ===================== rope + scatter to fp16 attention layouts =====================
__global__ void rope_scatter_kernel() {
    int idx = blockIdx.x*256 + threadIdx.x;
    if (idx >= NTOK*FTOT) return;
    int t = idx / FTOT;
    int f = idx - t*FTOT;
    int b = t >> 11;
    int s = t & (SEQ-1);
    float val = g_P[idx];
    int d = f & 63;
    if (f < 2560) {
        int j  = d & 31;
        float c  = g_cos[(s<<5) + j];
        float sn = g_sin[(s<<5) + j];
        float partner = g_P[idx + ((d & 32) ? -32 : 32)];
        float out = (d & 32) ? fmaf(partner, sn, val*c) : fmaf(-partner, sn, val*c);
        if (f < 2048) {
            int h = f >> 6;
            g_Qh[(((size_t)(b*NH + h))*SEQ + s)*HD + d] = __float2half_rn(out * QSC);
        } else {
            int g = (f - 2048) >> 6;
            g_Kh[(((size_t)(b*NG + g))*SEQ + s)*HD + d] = __float2half_rn(out);
        }
    } else {
        int g = (f - 2560) >> 6;
        g_Vh[(((size_t)(b*NG + g))*SEQ + s)*HD + d] = __float2half_rn(val);
    }
}

// ===================== fp16 HMMA flash attention =====================
// BQ=128 (8 warps x 16 rows), BK=64, double-buffered K/V.
// grid: (SEQ/128 = 16, BATCH*NH = 64)
__global__ __launch_bounds__(256)
void attn_mma_kernel()
{
    __shared__ __half Qs[128*64];
    __shared__ __half Ks[2][64*64];
    __shared__ __half Vs[2][64*64];

    const int tid = threadIdx.x, lane = tid & 31, wid = tid >> 5;
    const int qt = blockIdx.x, bh = blockIdx.y;
    const int b = bh >> 5, h = bh & 31, g = h >> 2;

    const __half* Qp = g_Qh + ((size_t)bh*SEQ + qt*128)*HD;
    const __half* Kp = g_Kh + ((size_t)(b*NG + g))*SEQ*HD;
    const __half* Vp = g_Vh + ((size_t)(b*NG + g))*SEQ*HD;

    const uint32_t qsb = smem_u32(Qs);
    const uint32_t ksb[2] = { smem_u32(Ks[0]), smem_u32(Ks[1]) };
    const uint32_t vsb[2] = { smem_u32(Vs[0]), smem_u32(Vs[1]) };

    // load Q (128 rows x 8 chunks) + prefetch K/V tile 0, one commit group
    {
        int r = tid >> 1, cb = (tid & 1) * 4;
#pragma unroll
        for (int c = 0; c < 4; c++)
            cp_async16(qsb + hswz(r, cb + c), Qp + r*64 + (cb + c)*8);
        int kr = tid >> 2, kc = (tid & 3) * 2;
#pragma unroll
        for (int c = 0; c < 2; c++) {
            cp_async16(ksb[0] + hswz(kr, kc + c), Kp + (size_t)kr*64 + (kc + c)*8);
            cp_async16(vsb[0] + hswz(kr, kc + c), Vp + (size_t)kr*64 + (kc + c)*8);
        }
        CP_COMMIT();
    }

    float o[8][4];
    float m[2] = {-1e30f, -1e30f}, l[2] = {0.f, 0.f};
#pragma unroll
    for (int f = 0; f < 8; f++)
#pragma unroll
        for (int e = 0; e < 4; e++) o[f][e] = 0.f;

    uint32_t qf[4][4];
    const int nkt = 2*qt + 2;

    for (int kt = 0; kt < nkt; kt++) {
        const int st = kt & 1;
        if (kt + 1 < nkt) {
            int kr = tid >> 2, kc = (tid & 3) * 2;
            const __half* Kn = Kp + (size_t)(kt + 1)*64*64;
            const __half* Vn = Vp + (size_t)(kt + 1)*64*64;
#pragma unroll
            for (int c = 0; c < 2; c++) {
                cp_async16(ksb[st^1] + hswz(kr, kc + c), Kn + (size_t)kr*64 + (kc + c)*8);
                cp_async16(vsb[st^1] + hswz(kr, kc + c), Vn + (size_t)kr*64 + (kc + c)*8);
            }
            CP_COMMIT();
            CP_WAIT(1);
        } else {
            CP_WAIT(0);
        }
        __syncthreads();

        if (kt == 0) {
#pragma unroll
            for (int kk = 0; kk < 4; kk++)
                ldsm4(qf[kk], qsb + hswz(wid*16 + (lane & 15), kk*2 + (lane >> 4)));
        }

        // S = Q K^T  (in log2 units; scale folded into Q)
        float s[8][4];
#pragma unroll
        for (int f = 0; f < 8; f++)
#pragma unroll
            for (int e = 0; e < 4; e++) s[f][e] = 0.f;

#pragma unroll
        for (int kk = 0; kk < 4; kk++) {
#pragma unroll
            for (int tb2 = 0; tb2 < 4; tb2++) {
                uint32_t kb[4];
                ldsm4(kb, ksb[st] + hswz((tb2*2 + ((lane >> 4) & 1))*8 + (lane & 7),
                                         kk*2 + ((lane >> 3) & 1)));
                mma16816h(s[tb2*2 + 0], qf[kk], &kb[0]);
                mma16816h(s[tb2*2 + 1], qf[kk], &kb[2]);
            }
        }

        // causal mask (only tiles that touch/cross the diagonal for this warp)
        if (kt*64 + 63 > qt*128 + wid*16) {
            int r0 = qt*128 + wid*16 + (lane >> 2);
#pragma unroll
            for (int f = 0; f < 8; f++) {
                int c0 = kt*64 + f*8 + (lane & 3)*2;
#pragma unroll
                for (int e = 0; e < 4; e++) {
                    int row = r0 + ((e >> 1) << 3);
                    int col = c0 + (e & 1);
                    if (col > row) s[f][e] = -1e30f;
                }
            }
        }

        // online softmax (base 2)
        float fsc[2];
#pragma unroll
        for (int rh = 0; rh < 2; rh++) {
            float mx = m[rh];
#pragma unroll
            for (int f = 0; f < 8; f++)
                mx = fmaxf(mx, fmaxf(s[f][2*rh], s[f][2*rh + 1]));
            mx = fmaxf(mx, __shfl_xor_sync(0xffffffffu, mx, 1));
            mx = fmaxf(mx, __shfl_xor_sync(0xffffffffu, mx, 2));
            fsc[rh] = exp2f(m[rh] - mx);
            float rs = 0.f;
#pragma unroll
            for (int f = 0; f < 8; f++) {
                s[f][2*rh]     = exp2f(s[f][2*rh]     - mx);
                s[f][2*rh + 1] = exp2f(s[f][2*rh + 1] - mx);
                rs += s[f][2*rh] + s[f][2*rh + 1];
            }
            rs += __shfl_xor_sync(0xffffffffu, rs, 1);
            rs += __shfl_xor_sync(0xffffffffu, rs, 2);
            l[rh] = l[rh]*fsc[rh] + rs;
            m[rh] = mx;
        }
#pragma unroll
        for (int f = 0; f < 8; f++) {
            o[f][0] *= fsc[0]; o[f][1] *= fsc[0];
            o[f][2] *= fsc[1]; o[f][3] *= fsc[1];
        }

        // P -> fp16 A-frags
        uint32_t pa[4][4];
#pragma unroll
        for (int kk = 0; kk < 4; kk++) {
            pa[kk][0] = pack_f16x2(s[2*kk][0],   s[2*kk][1]);
            pa[kk][1] = pack_f16x2(s[2*kk][2],   s[2*kk][3]);
            pa[kk][2] = pack_f16x2(s[2*kk+1][0], s[2*kk+1][1]);
            pa[kk][3] = pack_f16x2(s[2*kk+1][2], s[2*kk+1][3]);
        }

        // O += P V
#pragma unroll
        for (int kk = 0; kk < 4; kk++) {
#pragma unroll
            for (int db2 = 0; db2 < 4; db2++) {
                uint32_t vb[4];
                ldsm4t(vb, vsb[st] + hswz(kk*16 + ((lane >> 3) & 1)*8 + (lane & 7),
                                          db2*2 + ((lane >> 4) & 1)));
                mma16816h(o[db2*2 + 0], pa[kk], &vb[0]);
                mma16816h(o[db2*2 + 1], pa[kk], &vb[2]);
            }
        }
        __syncthreads();
    }

    // epilogue: normalize, write fp16 directly (O-proj consumes fp16)
    float inv0 = 1.f / l[0], inv1 = 1.f / l[1];
    int r0 = qt*128 + wid*16 + (lane >> 2);
    int t0 = b*SEQ + r0;
    uint32_t* AO32 = (uint32_t*)g_AOh;
#pragma unroll
    for (int f = 0; f < 8; f++) {
        int d = h*64 + f*8 + (lane & 3)*2;
        AO32[((size_t)t0*DM + d) >> 1]     = pack_f16x2(o[f][0]*inv0, o[f][1]*inv0);
        AO32[((size_t)(t0+8)*DM + d) >> 1] = pack_f16x2(o[f][2]*inv1, o[f][3]*inv1);
    }
}

// ===================== launch =====================
extern "C" void kernel_launch(void* const* d_in, const int* in_sizes, int n_in,
                              void* d_out, int out_size)
{
    const float* x  = (const float*)d_in[0];
    const float* Wq = (const float*)d_in[1];
    const float* bq = (const float*)d_in[2];
    const float* Wk = (const float*)d_in[3];
    const float* bk = (const float*)d_in[4];
    const float* Wv = (const float*)d_in[5];
    const float* bv = (const float*)d_in[6];
    const float* Wo = (const float*)d_in[7];
    const float* bo = (const float*)d_in[8];
    float* out = (float*)d_out;

    float *pP = nullptr;
    __half *pxh, *pWqh, *pWkh, *pWvh, *pWoh, *pAOh;
    cudaGetSymbolAddress((void**)&pP,   g_P);
    cudaGetSymbolAddress((void**)&pxh,  g_xh);
    cudaGetSymbolAddress((void**)&pWqh, g_Wqh);
    cudaGetSymbolAddress((void**)&pWkh, g_Wkh);
    cudaGetSymbolAddress((void**)&pWvh, g_Wvh);
    cudaGetSymbolAddress((void**)&pWoh, g_Woh);
    cudaGetSymbolAddress((void**)&pAOh, g_AOh);

    // fp32 -> fp16 conversions
    tohalf_kernel<<<(NTOK*DM/2)/256, 256>>>(x,  (uint32_t*)pxh,  NTOK*DM/2);
    tohalf_kernel<<<(DM*DM/2)/256,   256>>>(Wq, (uint32_t*)pWqh, DM*DM/2);
    tohalf_kernel<<<(512*DM/2)/256,  256>>>(Wk, (uint32_t*)pWkh, 512*DM/2);
    tohalf_kernel<<<(512*DM/2)/256,  256>>>(Wv, (uint32_t*)pWvh, 512*DM/2);
    tohalf_kernel<<<(DM*DM/2)/256,   256>>>(Wo, (uint32_t*)pWoh, DM*DM/2);

    // QKV projections (cols: q[0:2048), k[2048:2560), v[2560:3072))
    gemm_mma_kernel<<<dim3(DM/128,  NTOK/128), 256>>>(pxh, pWqh, bq, pP, DM, FTOT, 0);
    gemm_mma_kernel<<<dim3(512/128, NTOK/128), 256>>>(pxh, pWkh, bk, pP, DM, FTOT, 2048);
    gemm_mma_kernel<<<dim3(512/128, NTOK/128), 256>>>(pxh, pWvh, bv, pP, DM, FTOT, 2560);

    rope_table_kernel<<<(SEQ*32 + 255)/256, 256>>>();
    rope_scatter_kernel<<<(NTOK*FTOT)/256, 256>>>();

    attn_mma_kernel<<<dim3(SEQ/128, BATCH*NH), 256>>>();

    // output projection (A = fp16 attention output)
    gemm_mma_kernel<<<dim3(DM/128, NTOK/128), 256>>>(pAOh, pWoh, bo, out, DM, DM, 0);
}

// round 11
// speedup vs baseline: 7.4776x; 1.0647x over previous
#include <cuda_runtime.h>
#include <cuda_fp16.h>
#include <math.h>
#include <stdint.h>

#define SEQ   2048
#define DM    2048
#define NH    32
#define NG    8
#define HD    64
#define BATCH 2
#define NTOK  (BATCH*SEQ)   // 4096
#define FTOT  3072          // 2048 q + 512 k + 512 v

// fold softmax scale and log2(e) into Q (scores land in log2 domain)
#define QSC   (0.125f * 1.44269504088896340736f)

// ---------------- scratch (static device globals; no allocation) ----------------
__device__ float  g_P  [(size_t)NTOK*FTOT];
__device__ __half g_Qh [(size_t)BATCH*NH*SEQ*HD];
__device__ __half g_Kh [(size_t)BATCH*NG*SEQ*HD];
__device__ __half g_Vh [(size_t)BATCH*NG*SEQ*HD];
__device__ __half g_AOh[(size_t)NTOK*DM];
__device__ float  g_cos[SEQ*32];
__device__ float  g_sin[SEQ*32];

__device__ __half g_xh [(size_t)NTOK*DM];
__device__ __half g_Wqh[(size_t)DM *DM];
__device__ __half g_Wkh[(size_t)512*DM];
__device__ __half g_Wvh[(size_t)512*DM];
__device__ __half g_Woh[(size_t)DM *DM];

// ===================== helpers =====================
__device__ __forceinline__ uint32_t smem_u32(const void* p) {
    uint32_t a;
    asm("{ .reg .u64 t; cvta.to.shared.u64 t, %1; cvt.u32.u64 %0, t; }" : "=r"(a) : "l"(p));
    return a;
}
__device__ __forceinline__ void cp_async16(uint32_t dst, const void* src) {
    asm volatile("cp.async.cg.shared.global [%0], [%1], 16;" :: "r"(dst), "l"(src) : "memory");
}
#define CP_COMMIT() asm volatile("cp.async.commit_group;" ::: "memory")
#define CP_WAIT(n)  asm volatile("cp.async.wait_group %0;" :: "n"(n) : "memory")

__device__ __forceinline__ void ldsm4(uint32_t* r, uint32_t addr) {
    asm volatile("ldmatrix.sync.aligned.m8n8.x4.shared.b16 {%0,%1,%2,%3}, [%4];"
                 : "=r"(r[0]), "=r"(r[1]), "=r"(r[2]), "=r"(r[3]) : "r"(addr));
}
__device__ __forceinline__ void ldsm4t(uint32_t* r, uint32_t addr) {
    asm volatile("ldmatrix.sync.aligned.m8n8.x4.trans.shared.b16 {%0,%1,%2,%3}, [%4];"
                 : "=r"(r[0]), "=r"(r[1]), "=r"(r[2]), "=r"(r[3]) : "r"(addr));
}
__device__ __forceinline__ void mma16816h(float* d, const uint32_t* a, const uint32_t* b) {
    asm volatile("mma.sync.aligned.m16n8k16.row.col.f32.f16.f16.f32 "
                 "{%0,%1,%2,%3}, {%4,%5,%6,%7}, {%8,%9}, {%0,%1,%2,%3};"
                 : "+f"(d[0]), "+f"(d[1]), "+f"(d[2]), "+f"(d[3])
                 : "r"(a[0]), "r"(a[1]), "r"(a[2]), "r"(a[3]), "r"(b[0]), "r"(b[1]));
}
__device__ __forceinline__ uint32_t pack_f16x2(float lo, float hi) {
    uint32_t r;
    asm("cvt.rn.f16x2.f32 %0, %1, %2;" : "=r"(r) : "f"(hi), "f"(lo));
    return r;
}

// GEMM smem tile: rows x 32 halves (64B/row), swizzle: chunk' = chunk ^ ((row>>1)&3)
__device__ __forceinline__ uint32_t swz32(int row, int chunk) {
    return (uint32_t)(row*64 + ((chunk ^ ((row >> 1) & 3)) * 16));
}
// attention smem tile: rows of 64 halves (128B), swizzle: ch' = ch ^ (row&7)
__device__ __forceinline__ uint32_t hswz(int row, int ch) {
    return (uint32_t)(row*128 + ((ch ^ (row & 7)) * 16));
}

// ===================== fp32 -> fp16 conversion =====================
__global__ void tohalf_kernel(const float* __restrict__ src, uint32_t* __restrict__ dst, int npairs)
{
    int i = blockIdx.x*256 + threadIdx.x;
    if (i >= npairs) return;
    float2 v = ((const float2*)src)[i];
    dst[i] = pack_f16x2(v.x, v.y);
}

// ===================== shared GEMM body =====================
// Ap0 = A + bm*Kp  (fp16, K-major rows)
// Bp0 = W + local_n*Kp
// biasl: bias pointer offset to this block's 128-col segment
// Cb  = C + bm*ldc + global_col_base   (fp32 out)
__device__ __forceinline__ void gemm_body(const __half* __restrict__ Ap0,
                                          const __half* __restrict__ Bp0,
                                          const float* __restrict__ biasl,
                                          float* __restrict__ Cb,
                                          int Kp, int ldc)
{
    __shared__ __half As[2][128*32];
    __shared__ __half Bs[2][128*32];

    const int tid  = threadIdx.x;
    const int lane = tid & 31;
    const int wid  = tid >> 5;
    const int wm   = wid >> 2;
    const int wn   = wid & 3;

    const uint32_t asb[2] = { smem_u32(As[0]), smem_u32(As[1]) };
    const uint32_t bsb[2] = { smem_u32(Bs[0]), smem_u32(Bs[1]) };

    const int lrow = tid >> 2;
    const int lc   = tid & 3;

    float acc[4][4][4];
#pragma unroll
    for (int i = 0; i < 4; i++)
#pragma unroll
        for (int j = 0; j < 4; j++)
#pragma unroll
            for (int e = 0; e < 4; e++) acc[i][j][e] = 0.f;

    const int nk = Kp / 32;

    {
#pragma unroll
        for (int h = 0; h < 2; h++) {
            int row = lrow + h*64;
            cp_async16(asb[0] + swz32(row, lc), Ap0 + (size_t)row*Kp + lc*8);
            cp_async16(bsb[0] + swz32(row, lc), Bp0 + (size_t)row*Kp + lc*8);
        }
        CP_COMMIT();
    }

    for (int t = 0; t < nk; t++) {
        const int st = t & 1;
        if (t + 1 < nk) {
            const __half* Ap = Ap0 + (t+1)*32;
            const __half* Bp = Bp0 + (t+1)*32;
#pragma unroll
            for (int h = 0; h < 2; h++) {
                int row = lrow + h*64;
                cp_async16(asb[st^1] + swz32(row, lc), Ap + (size_t)row*Kp + lc*8);
                cp_async16(bsb[st^1] + swz32(row, lc), Bp + (size_t)row*Kp + lc*8);
            }
            CP_COMMIT();
            CP_WAIT(1);
        } else {
            CP_WAIT(0);
        }
        __syncthreads();

#pragma unroll
        for (int ks = 0; ks < 2; ks++) {
            uint32_t afr[4][4];
#pragma unroll
            for (int mf = 0; mf < 4; mf++) {
                int row = wm*64 + mf*16 + (lane & 15);
                int ch  = ks*2 + (lane >> 4);
                ldsm4(afr[mf], asb[st] + swz32(row, ch));
            }
            uint32_t bfr[2][4];
#pragma unroll
            for (int nb = 0; nb < 2; nb++) {
                int row = wn*32 + nb*16 + ((lane >> 4) << 3) + (lane & 7);
                int ch  = ks*2 + ((lane >> 3) & 1);
                ldsm4(bfr[nb], bsb[st] + swz32(row, ch));
            }
#pragma unroll
            for (int mf = 0; mf < 4; mf++) {
#pragma unroll
                for (int nb = 0; nb < 2; nb++) {
                    mma16816h(acc[mf][2*nb+0], afr[mf], &bfr[nb][0]);
                    mma16816h(acc[mf][2*nb+1], afr[mf], &bfr[nb][2]);
                }
            }
        }
        __syncthreads();
    }

#pragma unroll
    for (int mf = 0; mf < 4; mf++) {
        int ml = wm*64 + mf*16 + (lane >> 2);
#pragma unroll
        for (int nf = 0; nf < 4; nf++) {
            int nl = wn*32 + nf*8 + 2*(lane & 3);
            float b0 = biasl[nl], b1 = biasl[nl+1];
            float2 v0 = make_float2(acc[mf][nf][0] + b0, acc[mf][nf][1] + b1);
            float2 v1 = make_float2(acc[mf][nf][2] + b0, acc[mf][nf][3] + b1);
            *(float2*)(Cb + (size_t)ml*ldc + nl)     = v0;
            *(float2*)(Cb + (size_t)(ml+8)*ldc + nl) = v1;
        }
    }
}

// fused QKV: grid (24, 32); cols [0:2048)=Wq, [2048:2560)=Wk, [2560:3072)=Wv
__global__ __launch_bounds__(256, 2)
void qkv_gemm_kernel(const __half* __restrict__ xh,
                     const __half* __restrict__ Wq, const __half* __restrict__ Wk,
                     const __half* __restrict__ Wv,
                     const float* __restrict__ bq, const float* __restrict__ bk,
                     const float* __restrict__ bv,
                     float* __restrict__ P)
{
    const int bn = blockIdx.x * 128;
    const int bm = blockIdx.y * 128;
    const __half* W; const float* bias; int ln;
    if (bn < 2048)      { W = Wq; bias = bq; ln = bn; }
    else if (bn < 2560) { W = Wk; bias = bk; ln = bn - 2048; }
    else                { W = Wv; bias = bv; ln = bn - 2560; }
    gemm_body(xh + (size_t)bm*DM, W + (size_t)ln*DM, bias + ln,
              P + (size_t)bm*FTOT + bn, DM, FTOT);
}

// single GEMM (O projection)
__global__ __launch_bounds__(256, 2)
void gemm_mma_kernel(const __half* __restrict__ A, const __half* __restrict__ B,
                     const float* __restrict__ bias, float* __restrict__ C,
                     int Kp, int ldc)
{
    const int bn = blockIdx.x * 128;
    const int bm = blockIdx.y * 128;
    gemm_body(A + (size_t)bm*Kp, B + (size_t)bn*Kp, bias + bn,
              C + (size_t)bm*ldc + bn, Kp, ldc);
}

// ===================== RoPE table (fp64 pow once per j) =====================
// grid (SEQ/8, 1), block 256: tid = (pos_local<<5) | j
__global__ void rope_table_kernel() {
    __shared__ double th[32];
    int tid = threadIdx.x;
    if (tid < 32) th[tid] = pow(10000.0, -(double)tid / 32.0);
    __syncthreads();
    int j = tid & 31;
    int pos = blockIdx.x*8 + (tid >> 5);
    double d = (double)pos * th[j];
    const double TWO_PI = 6.283185307179586476925286766559;
    double r = d - floor(d * (1.0/TWO_PI)) * TWO_PI;
    float c, s;
    sincosf((float)r, &s, &c);
    g_cos[(pos<<5) + j] = c;
    g_sin[(pos<<5) + j] = s;
}

// ===================== rope + scatter (paired reads) =====================
// grid (7, NTOK), block 256: per token 1792 work items =
//   [0,1280): rope pairs (40 heads x 32 j)   [1280,1792): v elements
__global__ void rope_scatter_kernel() {
    int t = blockIdx.y;
    int w = blockIdx.x*256 + threadIdx.x;
    int b = t >> 11;
    int s = t & (SEQ-1);
    if (w < 1280) {
        int hh = w >> 5;     // 0..39: 32 q heads then 8 k groups
        int j  = w & 31;
        size_t pb = (size_t)t*FTOT + hh*64 + j;
        float v0 = g_P[pb];
        float v1 = g_P[pb + 32];
        float c  = g_cos[(s<<5) + j];
        float sn = g_sin[(s<<5) + j];
        float o0 = fmaf(-v1, sn, v0*c);
        float o1 = fmaf( v0, sn, v1*c);
        if (hh < 32) {
            size_t base = (((size_t)(b*NH + hh))*SEQ + s)*HD + j;
            g_Qh[base]      = __float2half_rn(o0 * QSC);
            g_Qh[base + 32] = __float2half_rn(o1 * QSC);
        } else {
            int g = hh - 32;
            size_t base = (((size_t)(b*NG + g))*SEQ + s)*HD + j;
            g_Kh[base]      = __float2half_rn(o0);
            g_Kh[base + 32] = __float2half_rn(o1);
        }
    } else {
        int r = w - 1280;    // 0..511
        int g = r >> 6, d = r & 63;
        float v = g_P[(size_t)t*FTOT + 2560 + r];
        g_Vh[(((size_t)(b*NG + g))*SEQ + s)*HD + d] = __float2half_rn(v);
    }
}

// ===================== fp16 HMMA flash attention =====================
// BQ=64 (4 warps x 16 rows), BK=64, double-buffered K/V, 3 CTAs/SM.
// grid: (SEQ/64 = 32, BATCH*NH = 64)
__global__ __launch_bounds__(128, 3)
void attn_mma_kernel()
{
    __shared__ __half Qs[64*64];
    __shared__ __half Ks[2][64*64];
    __shared__ __half Vs[2][64*64];

    const int tid = threadIdx.x, lane = tid & 31, wid = tid >> 5;
    const int qt = blockIdx.x, bh = blockIdx.y;
    const int b = bh >> 5, h = bh & 31, g = h >> 2;

    const __half* Qp = g_Qh + ((size_t)bh*SEQ + qt*64)*HD;
    const __half* Kp = g_Kh + ((size_t)(b*NG + g))*SEQ*HD;
    const __half* Vp = g_Vh + ((size_t)(b*NG + g))*SEQ*HD;

    const uint32_t qsb = smem_u32(Qs);
    const uint32_t ksb[2] = { smem_u32(Ks[0]), smem_u32(Ks[1]) };
    const uint32_t vsb[2] = { smem_u32(Vs[0]), smem_u32(Vs[1]) };

    // load Q + prefetch K/V tile 0 (64 rows x 8 chunks each; 128 thr -> 4/matrix)
    {
        int r = tid >> 1, cb = (tid & 1) * 4;
#pragma unroll
        for (int c = 0; c < 4; c++) {
            cp_async16(qsb + hswz(r, cb + c), Qp + r*64 + (cb + c)*8);
            cp_async16(ksb[0] + hswz(r, cb + c), Kp + (size_t)r*64 + (cb + c)*8);
            cp_async16(vsb[0] + hswz(r, cb + c), Vp + (size_t)r*64 + (cb + c)*8);
        }
        CP_COMMIT();
    }

    float o[8][4];
    float m[2] = {-1e30f, -1e30f}, l[2] = {0.f, 0.f};
#pragma unroll
    for (int f = 0; f < 8; f++)
#pragma unroll
        for (int e = 0; e < 4; e++) o[f][e] = 0.f;

    uint32_t qf[4][4];
    const int nkt = qt + 1;

    for (int kt = 0; kt < nkt; kt++) {
        const int st = kt & 1;
        if (kt + 1 < nkt) {
            int r = tid >> 1, cb = (tid & 1) * 4;
            const __half* Kn = Kp + (size_t)(kt + 1)*64*64;
            const __half* Vn = Vp + (size_t)(kt + 1)*64*64;
#pragma unroll
            for (int c = 0; c < 4; c++) {
                cp_async16(ksb[st^1] + hswz(r, cb + c), Kn + (size_t)r*64 + (cb + c)*8);
                cp_async16(vsb[st^1] + hswz(r, cb + c), Vn + (size_t)r*64 + (cb + c)*8);
            }
            CP_COMMIT();
            CP_WAIT(1);
        } else {
            CP_WAIT(0);
        }
        __syncthreads();

        if (kt == 0) {
#pragma unroll
            for (int kk = 0; kk < 4; kk++)
                ldsm4(qf[kk], qsb + hswz(wid*16 + (lane & 15), kk*2 + (lane >> 4)));
        }

        // S = Q K^T  (log2 units; scale folded into Q)
        float s[8][4];
#pragma unroll
        for (int f = 0; f < 8; f++)
#pragma unroll
            for (int e = 0; e < 4; e++) s[f][e] = 0.f;

#pragma unroll
        for (int kk = 0; kk < 4; kk++) {
#pragma unroll
            for (int tb2 = 0; tb2 < 4; tb2++) {
                uint32_t kb[4];
                ldsm4(kb, ksb[st] + hswz((tb2*2 + ((lane >> 4) & 1))*8 + (lane & 7),
                                         kk*2 + ((lane >> 3) & 1)));
                mma16816h(s[tb2*2 + 0], qf[kk], &kb[0]);
                mma16816h(s[tb2*2 + 1], qf[kk], &kb[2]);
            }
        }

        // causal mask (diagonal tile only)
        if (kt == qt) {
            int r0 = qt*64 + wid*16 + (lane >> 2);
#pragma unroll
            for (int f = 0; f < 8; f++) {
                int c0 = kt*64 + f*8 + (lane & 3)*2;
#pragma unroll
                for (int e = 0; e < 4; e++) {
                    int row = r0 + ((e >> 1) << 3);
                    int col = c0 + (e & 1);
                    if (col > row) s[f][e] = -1e30f;
                }
            }
        }

        // online softmax (base 2)
        float fsc[2];
#pragma unroll
        for (int rh = 0; rh < 2; rh++) {
            float mx = m[rh];
#pragma unroll
            for (int f = 0; f < 8; f++)
                mx = fmaxf(mx, fmaxf(s[f][2*rh], s[f][2*rh + 1]));
            mx = fmaxf(mx, __shfl_xor_sync(0xffffffffu, mx, 1));
            mx = fmaxf(mx, __shfl_xor_sync(0xffffffffu, mx, 2));
            fsc[rh] = exp2f(m[rh] - mx);
            float rs = 0.f;
#pragma unroll
            for (int f = 0; f < 8; f++) {
                s[f][2*rh]     = exp2f(s[f][2*rh]     - mx);
                s[f][2*rh + 1] = exp2f(s[f][2*rh + 1] - mx);
                rs += s[f][2*rh] + s[f][2*rh + 1];
            }
            rs += __shfl_xor_sync(0xffffffffu, rs, 1);
            rs += __shfl_xor_sync(0xffffffffu, rs, 2);
            l[rh] = l[rh]*fsc[rh] + rs;
            m[rh] = mx;
        }
#pragma unroll
        for (int f = 0; f < 8; f++) {
            o[f][0] *= fsc[0]; o[f][1] *= fsc[0];
            o[f][2] *= fsc[1]; o[f][3] *= fsc[1];
        }

        // P -> fp16 A-frags
        uint32_t pa[4][4];
#pragma unroll
        for (int kk = 0; kk < 4; kk++) {
            pa[kk][0] = pack_f16x2(s[2*kk][0],   s[2*kk][1]);
            pa[kk][1] = pack_f16x2(s[2*kk][2],   s[2*kk][3]);
            pa[kk][2] = pack_f16x2(s[2*kk+1][0], s[2*kk+1][1]);
            pa[kk][3] = pack_f16x2(s[2*kk+1][2], s[2*kk+1][3]);
        }

        // O += P V
#pragma unroll
        for (int kk = 0; kk < 4; kk++) {
#pragma unroll
            for (int db2 = 0; db2 < 4; db2++) {
                uint32_t vb[4];
                ldsm4t(vb, vsb[st] + hswz(kk*16 + ((lane >> 3) & 1)*8 + (lane & 7),
                                          db2*2 + ((lane >> 4) & 1)));
                mma16816h(o[db2*2 + 0], pa[kk], &vb[0]);
                mma16816h(o[db2*2 + 1], pa[kk], &vb[2]);
            }
        }
        __syncthreads();
    }

    // epilogue: normalize, write fp16
    float inv0 = 1.f / l[0], inv1 = 1.f / l[1];
    int r0 = qt*64 + wid*16 + (lane >> 2);
    int t0 = b*SEQ + r0;
    uint32_t* AO32 = (uint32_t*)g_AOh;
#pragma unroll
    for (int f = 0; f < 8; f++) {
        int d = h*64 + f*8 + (lane & 3)*2;
        AO32[((size_t)t0*DM + d) >> 1]     = pack_f16x2(o[f][0]*inv0, o[f][1]*inv0);
        AO32[((size_t)(t0+8)*DM + d) >> 1] = pack_f16x2(o[f][2]*inv1, o[f][3]*inv1);
    }
}

// ===================== launch =====================
extern "C" void kernel_launch(void* const* d_in, const int* in_sizes, int n_in,
                              void* d_out, int out_size)
{
    const float* x  = (const float*)d_in[0];
    const float* Wq = (const float*)d_in[1];
    const float* bq = (const float*)d_in[2];
    const float* Wk = (const float*)d_in[3];
    const float* bk = (const float*)d_in[4];
    const float* Wv = (const float*)d_in[5];
    const float* bv = (const float*)d_in[6];
    const float* Wo = (const float*)d_in[7];
    const float* bo = (const float*)d_in[8];
    float* out = (float*)d_out;

    float *pP = nullptr;
    __half *pxh, *pWqh, *pWkh, *pWvh, *pWoh, *pAOh;
    cudaGetSymbolAddress((void**)&pP,   g_P);
    cudaGetSymbolAddress((void**)&pxh,  g_xh);
    cudaGetSymbolAddress((void**)&pWqh, g_Wqh);
    cudaGetSymbolAddress((void**)&pWkh, g_Wkh);
    cudaGetSymbolAddress((void**)&pWvh, g_Wvh);
    cudaGetSymbolAddress((void**)&pWoh, g_Woh);
    cudaGetSymbolAddress((void**)&pAOh, g_AOh);

    // fp32 -> fp16 conversions
    tohalf_kernel<<<(NTOK*DM/2)/256, 256>>>(x,  (uint32_t*)pxh,  NTOK*DM/2);
    tohalf_kernel<<<(DM*DM/2)/256,   256>>>(Wq, (uint32_t*)pWqh, DM*DM/2);
    tohalf_kernel<<<(512*DM/2)/256,  256>>>(Wk, (uint32_t*)pWkh, 512*DM/2);
    tohalf_kernel<<<(512*DM/2)/256,  256>>>(Wv, (uint32_t*)pWvh, 512*DM/2);
    tohalf_kernel<<<(DM*DM/2)/256,   256>>>(Wo, (uint32_t*)pWoh, DM*DM/2);

    // fused QKV projection
    qkv_gemm_kernel<<<dim3(FTOT/128, NTOK/128), 256>>>(pxh, pWqh, pWkh, pWvh, bq, bk, bv, pP);

    rope_table_kernel<<<SEQ/8, 256>>>();
    rope_scatter_kernel<<<dim3(7, NTOK), 256>>>();

    attn_mma_kernel<<<dim3(SEQ/64, BATCH*NH), 128>>>();

    // output projection
    gemm_mma_kernel<<<dim3(DM/128, NTOK/128), 256>>>(pAOh, pWoh, bo, out, DM, DM);
}